// round 10
// baseline (speedup 1.0000x reference)
#include <cuda_runtime.h>
#include <cuda_bf16.h>
#include <math.h>

#define B_ 2
#define T_ 2048
#define D_ 2048
#define H_ 8
#define HD_ 128
#define C_ 1024
#define BT_ 64
#define NCH_ 32
#define M_ 4096
#define EPS_RMS 1.1920929e-07f

#define SZ_MC  ((size_t)M_*C_)
#define SZ_MH  ((size_t)M_*HD_)
#define SZ_BHT ((size_t)B_*H_*T_*HD_)

// pool offsets (in floats)
#define O_QLIN ((size_t)0)
#define O_KLIN (O_QLIN + SZ_MC)
#define O_VLIN (O_KLIN + SZ_MC)
#define O_ZA   (O_VLIN + SZ_MC)
#define O_ZG   (O_ZA + SZ_MC)
#define O_OG   (O_ZG + SZ_MC)
#define O_AD   (O_OG + SZ_MC)
#define O_GD   (O_AD + SZ_MH)
#define O_QH   (O_GD + SZ_MH)
#define O_KH   (O_QH + SZ_BHT)
#define O_VH   (O_KH + SZ_BHT)
#define O_GH   (O_VH + SZ_BHT)
#define O_QG   (O_GH + SZ_BHT)
#define O_KN   (O_QG + SZ_BHT)
#define O_W    (O_KN + SZ_BHT)
#define O_U    (O_W  + SZ_BHT)
#define O_O    (O_U  + SZ_BHT)
#define O_AQK  (O_O  + SZ_BHT)
#define O_EGL  (O_AQK + (size_t)B_*H_*NCH_*BT_*BT_)
#define POOL_SZ (O_EGL + (size_t)B_*H_*NCH_*HD_)

__device__ float g_pool[POOL_SZ];

// ---------------- generic SGEMM: C = A(MxK) @ B(KxN), row-major ----------------
// 128x128 tile, BK=8, 256 threads, 8x8 per thread. Requires M%128==0, N%128==0, K%8==0.
__global__ void __launch_bounds__(256) sgemm128(const float* __restrict__ A,
                                                const float* __restrict__ Bm,
                                                float* __restrict__ Cm,
                                                int M, int N, int K) {
    __shared__ float As[8][128];
    __shared__ float Bs[8][128];
    const int tid = threadIdx.x;
    const int tx = tid & 15, ty = tid >> 4;
    const int row0 = blockIdx.y * 128, col0 = blockIdx.x * 128;

    const int a_row = tid >> 1;
    const int a_k4  = (tid & 1) * 4;
    const int b_row = tid >> 5;
    const int b_col = (tid & 31) * 4;

    const float* Aptr = A + (size_t)(row0 + a_row) * K + a_k4;
    const float* Bptr = Bm + (size_t)b_row * N + col0 + b_col;

    float acc[8][8];
    #pragma unroll
    for (int r = 0; r < 8; r++)
        #pragma unroll
        for (int c = 0; c < 8; c++) acc[r][c] = 0.f;

    for (int kt = 0; kt < K; kt += 8) {
        float4 av = *(const float4*)(Aptr + kt);
        float4 bv = *(const float4*)(Bptr + (size_t)kt * N);
        As[a_k4 + 0][a_row] = av.x;
        As[a_k4 + 1][a_row] = av.y;
        As[a_k4 + 2][a_row] = av.z;
        As[a_k4 + 3][a_row] = av.w;
        *(float4*)&Bs[b_row][b_col] = bv;
        __syncthreads();
        #pragma unroll
        for (int k = 0; k < 8; k++) {
            float4 a0 = *(float4*)&As[k][ty * 8];
            float4 a1 = *(float4*)&As[k][ty * 8 + 4];
            float4 b0 = *(float4*)&Bs[k][tx * 8];
            float4 b1 = *(float4*)&Bs[k][tx * 8 + 4];
            float af[8] = {a0.x, a0.y, a0.z, a0.w, a1.x, a1.y, a1.z, a1.w};
            float bf[8] = {b0.x, b0.y, b0.z, b0.w, b1.x, b1.y, b1.z, b1.w};
            #pragma unroll
            for (int r = 0; r < 8; r++)
                #pragma unroll
                for (int c = 0; c < 8; c++)
                    acc[r][c] = fmaf(af[r], bf[c], acc[r][c]);
        }
        __syncthreads();
    }
    #pragma unroll
    for (int r = 0; r < 8; r++) {
        float* cp = Cm + (size_t)(row0 + ty * 8 + r) * N + col0 + tx * 8;
        float4 v0 = {acc[r][0], acc[r][1], acc[r][2], acc[r][3]};
        float4 v1 = {acc[r][4], acc[r][5], acc[r][6], acc[r][7]};
        *(float4*)cp = v0;
        *(float4*)(cp + 4) = v1;
    }
}

// ---------------- skinny SGEMM: N=128 fixed, BM=32, BK=16, 256 threads ----------------
__global__ void __launch_bounds__(256) sgemm_n128(const float* __restrict__ A,
                                                  const float* __restrict__ Bm,
                                                  float* __restrict__ Cm,
                                                  int K) {
    const int N = 128;
    __shared__ float As[16][33];
    __shared__ float Bs[16][128];
    const int tid = threadIdx.x;
    const int tx = tid & 31, ty = tid >> 5;
    const int row0 = blockIdx.x * 32;

    float acc[4][4];
    #pragma unroll
    for (int r = 0; r < 4; r++)
        #pragma unroll
        for (int c = 0; c < 4; c++) acc[r][c] = 0.f;

    for (int kt = 0; kt < K; kt += 16) {
        int e = tid * 2;
        int ar = e >> 4, ak = e & 15;
        float2 av = *(const float2*)&A[(size_t)(row0 + ar) * K + kt + ak];
        As[ak][ar] = av.x;
        As[ak + 1][ar] = av.y;
        #pragma unroll
        for (int q = 0; q < 2; q++) {
            int f = tid + q * 256;
            int br = f >> 5, bc = (f & 31) * 4;
            *(float4*)&Bs[br][bc] = *(const float4*)&Bm[(size_t)(kt + br) * N + bc];
        }
        __syncthreads();
        #pragma unroll
        for (int k = 0; k < 16; k++) {
            float4 b4 = *(float4*)&Bs[k][tx * 4];
            float bf[4] = {b4.x, b4.y, b4.z, b4.w};
            float af[4];
            #pragma unroll
            for (int r = 0; r < 4; r++) af[r] = As[k][ty * 4 + r];
            #pragma unroll
            for (int r = 0; r < 4; r++)
                #pragma unroll
                for (int c = 0; c < 4; c++)
                    acc[r][c] = fmaf(af[r], bf[c], acc[r][c]);
        }
        __syncthreads();
    }
    #pragma unroll
    for (int r = 0; r < 4; r++) {
        float4 v = {acc[r][0], acc[r][1], acc[r][2], acc[r][3]};
        *(float4*)&Cm[(size_t)(row0 + ty * 4 + r) * N + tx * 4] = v;
    }
}

// ---------------- conv + per-head L2 norm + silu + g; write head-major ----------------
__global__ void __launch_bounds__(128) convheads(
    const float* __restrict__ cqw, const float* __restrict__ cqb,
    const float* __restrict__ ckw, const float* __restrict__ ckb,
    const float* __restrict__ cvw, const float* __restrict__ cvb) {
    int h = blockIdx.x % H_;
    int bt = blockIdx.x / H_;
    int b = bt / T_, t = bt % T_;
    int d = threadIdx.x;
    int c = h * HD_ + d;
    size_t base = (size_t)bt * C_ + c;

    float qa = cqb[c], ka = ckb[c], va = cvb[c];
    #pragma unroll
    for (int j = 0; j < 4; j++) {
        int tt = t - 3 + j;
        if (tt >= 0) {
            size_t off = base - (size_t)(3 - j) * C_;
            qa = fmaf(g_pool[O_QLIN + off], cqw[c * 4 + j], qa);
            ka = fmaf(g_pool[O_KLIN + off], ckw[c * 4 + j], ka);
            va = fmaf(g_pool[O_VLIN + off], cvw[c * 4 + j], va);
        }
    }
    float s1 = qa * qa, s2 = ka * ka;
    #pragma unroll
    for (int o = 16; o > 0; o >>= 1) {
        s1 += __shfl_xor_sync(0xffffffffu, s1, o);
        s2 += __shfl_xor_sync(0xffffffffu, s2, o);
    }
    __shared__ float sh1[4], sh2[4];
    int w = threadIdx.x >> 5;
    if ((threadIdx.x & 31) == 0) { sh1[w] = s1; sh2[w] = s2; }
    __syncthreads();
    float qn = sh1[0] + sh1[1] + sh1[2] + sh1[3];
    float kn = sh2[0] + sh2[1] + sh2[2] + sh2[3];
    qa = qa / fmaxf(sqrtf(qn), 1e-12f);
    ka = ka / fmaxf(sqrtf(kn), 1e-12f);
    va = va / (1.f + expf(-va));
    float z = g_pool[O_ZA + base];
    float gg = fmaxf(-log1pf(expf(-z)), -13.815510557964274f);
    size_t ho = ((size_t)(b * H_ + h) * T_ + t) * HD_ + d;
    g_pool[O_QH + ho] = qa;
    g_pool[O_KH + ho] = ka;
    g_pool[O_VH + ho] = va;
    g_pool[O_GH + ho] = gg;
}

// ---------------- per-chunk: gc/exp transforms, Aqk, Akk, UT solve ----------------
__global__ void __launch_bounds__(256) chunkprep() {
    extern __shared__ float sm[];
    float* sQG  = sm;            // 64*132
    float* sKN  = sm + 8448;
    float* sKP  = sm + 16896;
    float* sV   = sm + 25344;
    float* sAqk = sm + 33792;    // 64*65
    float* sAkk = sm + 37952;
    float* ssol = sm;            // overlay on sQG+sKN (64*256 floats)

    int bhn = blockIdx.x;
    int bh = bhn >> 5, n = bhn & 31;
    int t0 = n * BT_;
    int tid = threadIdx.x;

    if (tid < 128) {
        int c = tid;
        float gc = 0.f;
        size_t gb = ((size_t)bh * T_ + t0) * HD_ + c;
        for (int t = 0; t < BT_; t++) {
            size_t gi = gb + (size_t)t * HD_;
            gc += g_pool[O_GH + gi];
            float ep = expf(gc), en = expf(-gc);
            float qv = g_pool[O_QH + gi];
            float kv = g_pool[O_KH + gi];
            float qg = qv * ep, knv = kv * en, kpv = kv * ep;
            sQG[t * 132 + c] = qg;
            sKN[t * 132 + c] = knv;
            sKP[t * 132 + c] = kpv;
            g_pool[O_QG + gi] = qg;
            g_pool[O_KN + gi] = knv;
        }
        g_pool[O_EGL + (size_t)bhn * HD_ + c] = expf(gc);
    } else {
        int c = tid - 128;
        size_t gb = ((size_t)bh * T_ + t0) * HD_ + c;
        for (int t = 0; t < BT_; t++)
            sV[t * 132 + c] = g_pool[O_VH + gb + (size_t)t * HD_];
    }
    __syncthreads();

    // Aqk[i][j] = QG[i]·KN[j] (j<=i);  Akk[i][j] = KN[i]·KP[j] (j<i)
    {
        int ty = tid >> 4, tx = tid & 15;
        float aqk[4][4], akk[4][4];
        #pragma unroll
        for (int r = 0; r < 4; r++)
            #pragma unroll
            for (int s = 0; s < 4; s++) { aqk[r][s] = 0.f; akk[r][s] = 0.f; }
        for (int k = 0; k < 128; k++) {
            float qgr[4], kni[4], knj[4], kps[4];
            #pragma unroll
            for (int r = 0; r < 4; r++) {
                qgr[r] = sQG[(ty * 4 + r) * 132 + k];
                kni[r] = sKN[(ty * 4 + r) * 132 + k];
            }
            #pragma unroll
            for (int s = 0; s < 4; s++) {
                knj[s] = sKN[(tx * 4 + s) * 132 + k];
                kps[s] = sKP[(tx * 4 + s) * 132 + k];
            }
            #pragma unroll
            for (int r = 0; r < 4; r++)
                #pragma unroll
                for (int s = 0; s < 4; s++) {
                    aqk[r][s] = fmaf(qgr[r], knj[s], aqk[r][s]);
                    akk[r][s] = fmaf(kni[r], kps[s], akk[r][s]);
                }
        }
        size_t ab = (size_t)bhn * 4096;
        #pragma unroll
        for (int r = 0; r < 4; r++)
            #pragma unroll
            for (int s = 0; s < 4; s++) {
                int i = ty * 4 + r, j = tx * 4 + s;
                float a = (j <= i) ? aqk[r][s] : 0.f;
                float kkv = (j < i) ? akk[r][s] : 0.f;
                sAqk[i * 65 + j] = a;
                sAkk[i * 65 + j] = kkv;
                g_pool[O_AQK + ab + (size_t)i * 64 + j] = a;
            }
    }
    __syncthreads();

    // forward substitution: (I + Akk_strict) sol = [KP | V]; thread = column
    {
        int col = tid;
        for (int i = 0; i < BT_; i++) {
            float val = (col < 128) ? sKP[i * 132 + col] : sV[i * 132 + (col - 128)];
            for (int j = 0; j < i; j++)
                val = fmaf(-sAkk[i * 65 + j], ssol[j * 256 + col], val);
            ssol[i * 256 + col] = val;
        }
    }
    __syncthreads();
    {
        int col = tid;
        size_t gb = ((size_t)bh * T_ + t0) * HD_ + (col & 127);
        for (int i = 0; i < BT_; i++) {
            float v = ssol[i * 256 + col];
            if (col < 128) g_pool[O_W + gb + (size_t)i * HD_] = v;
            else           g_pool[O_U + gb + (size_t)i * HD_] = v;
        }
    }
}

// ---------------- sequential scan over chunks; 8-way V split ----------------
__global__ void __launch_bounds__(256) scan_kernel(float* Sout) {
    extern __shared__ float sm[];
    float* sS   = sm;            // 128*16
    float* sW   = sm + 2048;     // 64*132
    float* sQG  = sm + 10496;
    float* sKN  = sm + 18944;
    float* sAqk = sm + 27392;    // 64*65
    float* sU   = sm + 31552;    // 64*16
    float* sT2  = sm + 32576;    // 64*16
    float* egl  = sm + 33600;    // 128

    int bh = blockIdx.x >> 3, vs = blockIdx.x & 7;
    int tid = threadIdx.x;
    int v = tid & 15, cq = tid >> 4;

    for (int e = tid; e < 2048; e += 256) sS[e] = 0.f;

    for (int n = 0; n < NCH_; n++) {
        __syncthreads();
        size_t tb = ((size_t)bh * T_ + n * BT_) * HD_;
        for (int e = tid; e < 8192; e += 256) {
            int t = e >> 7, c = e & 127;
            sW[t * 132 + c]  = g_pool[O_W + tb + e];
            sQG[t * 132 + c] = g_pool[O_QG + tb + e];
            sKN[t * 132 + c] = g_pool[O_KN + tb + e];
        }
        size_t ab = (size_t)(bh * NCH_ + n) * 4096;
        for (int e = tid; e < 4096; e += 256)
            sAqk[(e >> 6) * 65 + (e & 63)] = g_pool[O_AQK + ab + e];
        for (int e = tid; e < 1024; e += 256) {
            int t = e >> 4, vv = e & 15;
            sU[t * 16 + vv] = g_pool[O_U + tb + (size_t)t * HD_ + vs * 16 + vv];
        }
        if (tid < 128) egl[tid] = g_pool[O_EGL + (size_t)(bh * NCH_ + n) * HD_ + tid];
        __syncthreads();

        // t1 = W @ S_slice, t2 = U - t1
        float t1[4] = {0.f, 0.f, 0.f, 0.f};
        for (int k = 0; k < 128; k++) {
            float sv = sS[k * 16 + v];
            #pragma unroll
            for (int r = 0; r < 4; r++)
                t1[r] = fmaf(sW[(cq * 4 + r) * 132 + k], sv, t1[r]);
        }
        #pragma unroll
        for (int r = 0; r < 4; r++) {
            int c = cq * 4 + r;
            sT2[c * 16 + v] = sU[c * 16 + v] - t1[r];
        }
        __syncthreads();

        // o = QG @ S + Aqk @ t2
        float oa[4] = {0.f, 0.f, 0.f, 0.f};
        for (int k = 0; k < 128; k++) {
            float sv = sS[k * 16 + v];
            #pragma unroll
            for (int r = 0; r < 4; r++)
                oa[r] = fmaf(sQG[(cq * 4 + r) * 132 + k], sv, oa[r]);
        }
        for (int j = 0; j < 64; j++) {
            float tv = sT2[j * 16 + v];
            #pragma unroll
            for (int r = 0; r < 4; r++)
                oa[r] = fmaf(sAqk[(cq * 4 + r) * 65 + j], tv, oa[r]);
        }
        #pragma unroll
        for (int r = 0; r < 4; r++)
            g_pool[O_O + tb + (size_t)(cq * 4 + r) * HD_ + vs * 16 + v] = oa[r];
        __syncthreads();

        // S = e^{g_last} * (S + KN^T @ U)
        float acc[8];
        #pragma unroll
        for (int r = 0; r < 8; r++) acc[r] = 0.f;
        for (int c = 0; c < 64; c++) {
            float uv = sU[c * 16 + v];
            #pragma unroll
            for (int r = 0; r < 8; r++)
                acc[r] = fmaf(sKN[c * 132 + cq * 8 + r], uv, acc[r]);
        }
        #pragma unroll
        for (int r = 0; r < 8; r++) {
            int k = cq * 8 + r;
            sS[k * 16 + v] = egl[k] * (sS[k * 16 + v] + acc[r]);
        }
    }
    if (Sout) {
        __syncthreads();
        #pragma unroll
        for (int r = 0; r < 8; r++) {
            int k = cq * 8 + r;
            Sout[((size_t)bh * HD_ + k) * HD_ + vs * 16 + v] = sS[k * 16 + v];
        }
    }
}

// ---------------- RMS norm + gate ----------------
__global__ void __launch_bounds__(128) epilogue(const float* __restrict__ normw) {
    int h = blockIdx.x % H_;
    int bt = blockIdx.x / H_;
    int b = bt / T_, t = bt % T_;
    int d = threadIdx.x;
    float o = g_pool[O_O + ((size_t)(b * H_ + h) * T_ + t) * HD_ + d];
    float s = o * o;
    #pragma unroll
    for (int off = 16; off > 0; off >>= 1) s += __shfl_xor_sync(0xffffffffu, s, off);
    __shared__ float sh[4];
    int w = threadIdx.x >> 5;
    if ((threadIdx.x & 31) == 0) sh[w] = s;
    __syncthreads();
    float ms = (sh[0] + sh[1] + sh[2] + sh[3]) * (1.f / 128.f);
    size_t gi = (size_t)bt * C_ + h * HD_ + d;
    float z = g_pool[O_ZG + gi];
    float gate = 1.f / (1.f + expf(-z));
    g_pool[O_OG + gi] = o * rsqrtf(ms + EPS_RMS) * normw[d] * gate;
}

extern "C" void kernel_launch(void* const* d_in, const int* in_sizes, int n_in,
                              void* d_out, int out_size) {
    const float* x     = (const float*)d_in[0];
    const float* Wq    = (const float*)d_in[1];
    const float* Wk    = (const float*)d_in[2];
    const float* Wv    = (const float*)d_in[3];
    const float* cqw   = (const float*)d_in[4];
    const float* cqb   = (const float*)d_in[5];
    const float* ckw   = (const float*)d_in[6];
    const float* ckb   = (const float*)d_in[7];
    const float* cvw   = (const float*)d_in[8];
    const float* cvb   = (const float*)d_in[9];
    const float* Wad   = (const float*)d_in[10];
    const float* Wau   = (const float*)d_in[11];
    // d_in[12] = Wb (unused by reference output)
    const float* Wgd   = (const float*)d_in[13];
    const float* Wgu   = (const float*)d_in[14];
    const float* normw = (const float*)d_in[15];
    const float* Wo    = (const float*)d_in[16];
    float* out = (float*)d_out;

    void* pv = nullptr;
    cudaGetSymbolAddress(&pv, g_pool);
    float* pool = (float*)pv;

    cudaFuncSetAttribute(chunkprep, cudaFuncAttributeMaxDynamicSharedMemorySize, 42112 * 4);
    cudaFuncSetAttribute(scan_kernel, cudaFuncAttributeMaxDynamicSharedMemorySize, 33728 * 4);

    // 1) projections
    sgemm128<<<dim3(C_ / 128, M_ / 128), 256>>>(x, Wq, pool + O_QLIN, M_, C_, D_);
    sgemm128<<<dim3(C_ / 128, M_ / 128), 256>>>(x, Wk, pool + O_KLIN, M_, C_, D_);
    sgemm128<<<dim3(C_ / 128, M_ / 128), 256>>>(x, Wv, pool + O_VLIN, M_, C_, D_);
    sgemm_n128<<<M_ / 32, 256>>>(x, Wad, pool + O_AD, D_);
    sgemm_n128<<<M_ / 32, 256>>>(x, Wgd, pool + O_GD, D_);
    sgemm128<<<dim3(C_ / 128, M_ / 128), 256>>>(pool + O_AD, Wau, pool + O_ZA, M_, C_, HD_);
    sgemm128<<<dim3(C_ / 128, M_ / 128), 256>>>(pool + O_GD, Wgu, pool + O_ZG, M_, C_, HD_);

    // 2) conv + norms + silu + g
    convheads<<<B_ * T_ * H_, 128>>>(cqw, cqb, ckw, ckb, cvw, cvb);

    // 3) per-chunk prep (parallel over 512 chunks)
    chunkprep<<<B_ * H_ * NCH_, 256, 42112 * 4>>>();

    // 4) sequential scan, 8-way V split (128 blocks)
    float* Sout = nullptr;
    size_t ysz = (size_t)M_ * D_;
    size_t ssz = (size_t)B_ * H_ * HD_ * HD_;
    if ((size_t)out_size >= ysz + ssz) Sout = out + ysz;
    scan_kernel<<<B_ * H_ * 8, 256, 33728 * 4>>>(Sout);

    // 5) rms norm + gate
    epilogue<<<B_ * T_ * H_, 128>>>(normw);

    // 6) final projection -> d_out
    sgemm128<<<dim3(D_ / 128, M_ / 128), 256>>>(pool + O_OG, Wo, out, M_, D_, C_);
}

// round 15
// speedup vs baseline: 1.6998x; 1.6998x over previous
#include <cuda_runtime.h>
#include <cuda_bf16.h>
#include <math.h>
#include <stdint.h>

#define B_ 2
#define T_ 2048
#define D_ 2048
#define H_ 8
#define HD_ 128
#define C_ 1024
#define BT_ 64
#define NCH_ 32
#define M_ 4096
#define EPS_RMS 1.1920929e-07f

#define SZ_MC  ((size_t)M_*C_)
#define SZ_MH  ((size_t)M_*HD_)
#define SZ_BHT ((size_t)B_*H_*T_*HD_)

// ---------------- fp32 scratch pool ----------------
#define O_QLIN ((size_t)0)
#define O_KLIN (O_QLIN + SZ_MC)
#define O_VLIN (O_KLIN + SZ_MC)
#define O_ZA   (O_VLIN + SZ_MC)
#define O_ZG   (O_ZA + SZ_MC)
#define O_OG   (O_ZG + SZ_MC)
#define O_AD   (O_OG + SZ_MC)
#define O_GD   (O_AD + SZ_MH)
#define O_QH   (O_GD + SZ_MH)
#define O_KH   (O_QH + SZ_BHT)
#define O_VH   (O_KH + SZ_BHT)
#define O_GH   (O_VH + SZ_BHT)
#define O_QG   (O_GH + SZ_BHT)
#define O_KN   (O_QG + SZ_BHT)
#define O_W    (O_KN + SZ_BHT)
#define O_U    (O_W  + SZ_BHT)
#define O_O    (O_U  + SZ_BHT)
#define O_AQK  (O_O  + SZ_BHT)
#define O_EGL  (O_AQK + (size_t)B_*H_*NCH_*BT_*BT_)
#define POOL_SZ (O_EGL + (size_t)B_*H_*NCH_*HD_)

__device__ __align__(128) float g_pool[POOL_SZ];

// ---------------- bf16 split scratch pool ----------------
#define SB_X   ((size_t)M_*D_)
#define SB_W   ((size_t)D_*C_)
#define SB_WAD ((size_t)D_*HD_)
#define SB_WAU ((size_t)HD_*C_)
#define SB_AD  ((size_t)M_*HD_)
#define SB_OG  ((size_t)M_*C_)

#define BO_XHI   ((size_t)0)
#define BO_XLO   (BO_XHI + SB_X)
#define BO_WQTH  (BO_XLO + SB_X)
#define BO_WQTL  (BO_WQTH + SB_W)
#define BO_WKTH  (BO_WQTL + SB_W)
#define BO_WKTL  (BO_WKTH + SB_W)
#define BO_WVTH  (BO_WKTL + SB_W)
#define BO_WVTL  (BO_WVTH + SB_W)
#define BO_WOTH  (BO_WVTL + SB_W)
#define BO_WOTL  (BO_WOTH + SB_W)
#define BO_WADTH (BO_WOTL + SB_W)
#define BO_WADTL (BO_WADTH + SB_WAD)
#define BO_WGDTH (BO_WADTL + SB_WAD)
#define BO_WGDTL (BO_WGDTH + SB_WAD)
#define BO_WAUTH (BO_WGDTL + SB_WAD)
#define BO_WAUTL (BO_WAUTH + SB_WAU)
#define BO_WGUTH (BO_WAUTL + SB_WAU)
#define BO_WGUTL (BO_WGUTH + SB_WAU)
#define BO_ADH   (BO_WGUTL + SB_WAU)
#define BO_ADL   (BO_ADH + SB_AD)
#define BO_GDH   (BO_ADL + SB_AD)
#define BO_GDL   (BO_GDH + SB_AD)
#define BO_OGH   (BO_GDL + SB_AD)
#define BO_OGL   (BO_OGH + SB_OG)
#define BPOOL_SZ (BO_OGL + SB_OG)

__device__ __align__(128) __nv_bfloat16 g_bpool[BPOOL_SZ];

// ---------------- warp MMA helpers (sm_80+ PTX, valid on base sm_103) ----------------
__device__ __forceinline__ uint32_t smem_u32(const void* p) {
    return (uint32_t)__cvta_generic_to_shared(p);
}

__device__ __forceinline__ void mma16816(float* d, const uint32_t* a, const uint32_t* b) {
    asm volatile(
        "mma.sync.aligned.m16n8k16.row.col.f32.bf16.bf16.f32 "
        "{%0,%1,%2,%3}, {%4,%5,%6,%7}, {%8,%9}, {%0,%1,%2,%3};"
        : "+f"(d[0]), "+f"(d[1]), "+f"(d[2]), "+f"(d[3])
        : "r"(a[0]), "r"(a[1]), "r"(a[2]), "r"(a[3]), "r"(b[0]), "r"(b[1]));
}

__device__ __forceinline__ void ldsm4(uint32_t* r, uint32_t addr) {
    asm volatile("ldmatrix.sync.aligned.m8n8.x4.shared.b16 {%0,%1,%2,%3}, [%4];"
        : "=r"(r[0]), "=r"(r[1]), "=r"(r[2]), "=r"(r[3]) : "r"(addr));
}

__device__ __forceinline__ void ldsm2(uint32_t* r, uint32_t addr) {
    asm volatile("ldmatrix.sync.aligned.m8n8.x2.shared.b16 {%0,%1}, [%2];"
        : "=r"(r[0]), "=r"(r[1]) : "r"(addr));
}

// ---------------- split conversion (elementwise, float4) ----------------
__global__ void __launch_bounds__(256) cvt_split(const float* __restrict__ s,
                                                 __nv_bfloat16* __restrict__ hi,
                                                 __nv_bfloat16* __restrict__ lo,
                                                 int n4) {
    int i = blockIdx.x * 256 + threadIdx.x;
    if (i >= n4) return;
    float4 v = ((const float4*)s)[i];
    float f[4] = {v.x, v.y, v.z, v.w};
    __nv_bfloat16 h[4], l[4];
    #pragma unroll
    for (int j = 0; j < 4; j++) {
        h[j] = __float2bfloat16(f[j]);
        l[j] = __float2bfloat16(f[j] - __bfloat162float(h[j]));
    }
    __nv_bfloat162 h0 = {h[0], h[1]}, h1 = {h[2], h[3]};
    __nv_bfloat162 l0 = {l[0], l[1]}, l1 = {l[2], l[3]};
    ((__nv_bfloat162*)hi)[2 * i] = h0;
    ((__nv_bfloat162*)hi)[2 * i + 1] = h1;
    ((__nv_bfloat162*)lo)[2 * i] = l0;
    ((__nv_bfloat162*)lo)[2 * i + 1] = l1;
}

// ---------------- transpose + split: W[K,N] -> Wt[N,K] ----------------
__global__ void __launch_bounds__(256) cvt_splitT(const float* __restrict__ W,
                                                  __nv_bfloat16* __restrict__ hi,
                                                  __nv_bfloat16* __restrict__ lo,
                                                  int K, int N) {
    __shared__ float tile[32][33];
    int n0 = blockIdx.x * 32, k0 = blockIdx.y * 32;
    int tx = threadIdx.x & 31, ty = threadIdx.x >> 5;
    #pragma unroll
    for (int j = 0; j < 32; j += 8)
        tile[ty + j][tx] = W[(size_t)(k0 + ty + j) * N + n0 + tx];
    __syncthreads();
    #pragma unroll
    for (int j = 0; j < 32; j += 8) {
        float v = tile[tx][ty + j];
        __nv_bfloat16 h = __float2bfloat16(v);
        size_t o = (size_t)(n0 + ty + j) * K + k0 + tx;
        hi[o] = h;
        lo[o] = __float2bfloat16(v - __bfloat162float(h));
    }
}

// ---------------- split-bf16 tensor-core GEMM via mma.sync ----------------
// C[M,N] (fp32) = (Ah+Al)[M,K] @ (Bh+Bl)[N,K]^T   (3-product compensation)
// Tile 128x128, K-step 64. 256 threads = 8 warps in 2x4 grid, each warp 64x32.
#define TPAD 72
#define TG_SMEM (4 * 128 * TPAD * 2)

__global__ void __launch_bounds__(256) tgemm(
    const __nv_bfloat16* __restrict__ Ah, const __nv_bfloat16* __restrict__ Al,
    const __nv_bfloat16* __restrict__ Bh, const __nv_bfloat16* __restrict__ Bl,
    float* __restrict__ Cm, int M, int N, int K) {
    extern __shared__ __nv_bfloat16 ts[];
    __nv_bfloat16* sAh = ts;
    __nv_bfloat16* sAl = ts + 128 * TPAD;
    __nv_bfloat16* sBh = ts + 2 * 128 * TPAD;
    __nv_bfloat16* sBl = ts + 3 * 128 * TPAD;

    const int tid = threadIdx.x;
    const int lane = tid & 31, w = tid >> 5;
    const int wr = w >> 2, wc = w & 3;
    const int row0 = blockIdx.y * 128, col0 = blockIdx.x * 128;

    float acc[4][4][4];
    #pragma unroll
    for (int mt = 0; mt < 4; mt++)
        #pragma unroll
        for (int nt = 0; nt < 4; nt++)
            #pragma unroll
            for (int e = 0; e < 4; e++) acc[mt][nt][e] = 0.f;

    const int lr = tid >> 3;            // load row 0..31 base (4 iters cover 128)
    const int lc = (tid & 7) << 3;      // bf16 col 0..56

    for (int kb = 0; kb < K; kb += 64) {
        #pragma unroll
        for (int j = 0; j < 4; j++) {
            int r = lr + j * 32;
            size_t ga = (size_t)(row0 + r) * K + kb + lc;
            size_t gb = (size_t)(col0 + r) * K + kb + lc;
            *(uint4*)&sAh[r * TPAD + lc] = *(const uint4*)(Ah + ga);
            *(uint4*)&sAl[r * TPAD + lc] = *(const uint4*)(Al + ga);
            *(uint4*)&sBh[r * TPAD + lc] = *(const uint4*)(Bh + gb);
            *(uint4*)&sBl[r * TPAD + lc] = *(const uint4*)(Bl + gb);
        }
        __syncthreads();

        #pragma unroll
        for (int ks = 0; ks < 4; ks++) {
            const int k16 = ks * 16;
            uint32_t bh[4][2], bl[4][2];
            const int l16 = lane & 15;
            #pragma unroll
            for (int nt = 0; nt < 4; nt++) {
                int nr = wc * 32 + nt * 8 + (l16 & 7);
                int kc = k16 + ((l16 >> 3) << 3);
                ldsm2(bh[nt], smem_u32(&sBh[nr * TPAD + kc]));
                ldsm2(bl[nt], smem_u32(&sBl[nr * TPAD + kc]));
            }
            #pragma unroll
            for (int mt = 0; mt < 4; mt++) {
                int mr = wr * 64 + mt * 16 + (lane & 15);
                int kc = k16 + ((lane >> 4) << 3);
                uint32_t ah4[4], al4[4];
                ldsm4(ah4, smem_u32(&sAh[mr * TPAD + kc]));
                ldsm4(al4, smem_u32(&sAl[mr * TPAD + kc]));
                #pragma unroll
                for (int nt = 0; nt < 4; nt++) {
                    mma16816(acc[mt][nt], ah4, bh[nt]);
                    mma16816(acc[mt][nt], ah4, bl[nt]);
                    mma16816(acc[mt][nt], al4, bh[nt]);
                }
            }
        }
        __syncthreads();
    }

    // epilogue: d0,d1 at (row, col..col+1); d2,d3 at (row+8, col..col+1)
    #pragma unroll
    for (int mt = 0; mt < 4; mt++) {
        int row = row0 + wr * 64 + mt * 16 + (lane >> 2);
        #pragma unroll
        for (int nt = 0; nt < 4; nt++) {
            int col = col0 + wc * 32 + nt * 8 + 2 * (lane & 3);
            float* cp = Cm + (size_t)row * N + col;
            float2 v0 = {acc[mt][nt][0], acc[mt][nt][1]};
            float2 v1 = {acc[mt][nt][2], acc[mt][nt][3]};
            *(float2*)cp = v0;
            *(float2*)(cp + 8 * (size_t)N) = v1;
        }
    }
}

// ---------------- conv + per-head L2 norm + silu + g; write head-major ----------------
__global__ void __launch_bounds__(128) convheads(
    const float* __restrict__ cqw, const float* __restrict__ cqb,
    const float* __restrict__ ckw, const float* __restrict__ ckb,
    const float* __restrict__ cvw, const float* __restrict__ cvb) {
    int h = blockIdx.x % H_;
    int bt = blockIdx.x / H_;
    int b = bt / T_, t = bt % T_;
    int d = threadIdx.x;
    int c = h * HD_ + d;
    size_t base = (size_t)bt * C_ + c;

    float qa = cqb[c], ka = ckb[c], va = cvb[c];
    #pragma unroll
    for (int j = 0; j < 4; j++) {
        int tt = t - 3 + j;
        if (tt >= 0) {
            size_t off = base - (size_t)(3 - j) * C_;
            qa = fmaf(g_pool[O_QLIN + off], cqw[c * 4 + j], qa);
            ka = fmaf(g_pool[O_KLIN + off], ckw[c * 4 + j], ka);
            va = fmaf(g_pool[O_VLIN + off], cvw[c * 4 + j], va);
        }
    }
    float s1 = qa * qa, s2 = ka * ka;
    #pragma unroll
    for (int o = 16; o > 0; o >>= 1) {
        s1 += __shfl_xor_sync(0xffffffffu, s1, o);
        s2 += __shfl_xor_sync(0xffffffffu, s2, o);
    }
    __shared__ float sh1[4], sh2[4];
    int w = threadIdx.x >> 5;
    if ((threadIdx.x & 31) == 0) { sh1[w] = s1; sh2[w] = s2; }
    __syncthreads();
    float qn = sh1[0] + sh1[1] + sh1[2] + sh1[3];
    float kn = sh2[0] + sh2[1] + sh2[2] + sh2[3];
    qa = qa / fmaxf(sqrtf(qn), 1e-12f);
    ka = ka / fmaxf(sqrtf(kn), 1e-12f);
    va = va / (1.f + expf(-va));
    float z = g_pool[O_ZA + base];
    float gg = fmaxf(-log1pf(expf(-z)), -13.815510557964274f);
    size_t ho = ((size_t)(b * H_ + h) * T_ + t) * HD_ + d;
    g_pool[O_QH + ho] = qa;
    g_pool[O_KH + ho] = ka;
    g_pool[O_VH + ho] = va;
    g_pool[O_GH + ho] = gg;
}

// ---------------- per-chunk: gc/exp transforms, Aqk, Akk, UT solve ----------------
__global__ void __launch_bounds__(256) chunkprep() {
    extern __shared__ float sm[];
    float* sQG  = sm;            // 64*132
    float* sKN  = sm + 8448;
    float* sKP  = sm + 16896;
    float* sV   = sm + 25344;
    float* sAqk = sm + 33792;    // 64*65
    float* sAkk = sm + 37952;
    float* ssol = sm;            // overlay on sQG+sKN

    int bhn = blockIdx.x;
    int bh = bhn >> 5, n = bhn & 31;
    int t0 = n * BT_;
    int tid = threadIdx.x;

    if (tid < 128) {
        int c = tid;
        float gc = 0.f;
        size_t gb = ((size_t)bh * T_ + t0) * HD_ + c;
        for (int t = 0; t < BT_; t++) {
            size_t gi = gb + (size_t)t * HD_;
            gc += g_pool[O_GH + gi];
            float ep = expf(gc), en = expf(-gc);
            float qv = g_pool[O_QH + gi];
            float kv = g_pool[O_KH + gi];
            float qg = qv * ep, knv = kv * en, kpv = kv * ep;
            sQG[t * 132 + c] = qg;
            sKN[t * 132 + c] = knv;
            sKP[t * 132 + c] = kpv;
            g_pool[O_QG + gi] = qg;
            g_pool[O_KN + gi] = knv;
        }
        g_pool[O_EGL + (size_t)bhn * HD_ + c] = expf(gc);
    } else {
        int c = tid - 128;
        size_t gb = ((size_t)bh * T_ + t0) * HD_ + c;
        for (int t = 0; t < BT_; t++)
            sV[t * 132 + c] = g_pool[O_VH + gb + (size_t)t * HD_];
    }
    __syncthreads();

    {
        int ty = tid >> 4, tx = tid & 15;
        float aqk[4][4], akk[4][4];
        #pragma unroll
        for (int r = 0; r < 4; r++)
            #pragma unroll
            for (int s = 0; s < 4; s++) { aqk[r][s] = 0.f; akk[r][s] = 0.f; }
        for (int k = 0; k < 128; k++) {
            float qgr[4], kni[4], knj[4], kps[4];
            #pragma unroll
            for (int r = 0; r < 4; r++) {
                qgr[r] = sQG[(ty * 4 + r) * 132 + k];
                kni[r] = sKN[(ty * 4 + r) * 132 + k];
            }
            #pragma unroll
            for (int s = 0; s < 4; s++) {
                knj[s] = sKN[(tx * 4 + s) * 132 + k];
                kps[s] = sKP[(tx * 4 + s) * 132 + k];
            }
            #pragma unroll
            for (int r = 0; r < 4; r++)
                #pragma unroll
                for (int s = 0; s < 4; s++) {
                    aqk[r][s] = fmaf(qgr[r], knj[s], aqk[r][s]);
                    akk[r][s] = fmaf(kni[r], kps[s], akk[r][s]);
                }
        }
        size_t ab = (size_t)bhn * 4096;
        #pragma unroll
        for (int r = 0; r < 4; r++)
            #pragma unroll
            for (int s = 0; s < 4; s++) {
                int i = ty * 4 + r, j = tx * 4 + s;
                float a = (j <= i) ? aqk[r][s] : 0.f;
                float kkv = (j < i) ? akk[r][s] : 0.f;
                sAqk[i * 65 + j] = a;
                sAkk[i * 65 + j] = kkv;
                g_pool[O_AQK + ab + (size_t)i * 64 + j] = a;
            }
    }
    __syncthreads();

    {
        int col = tid;
        for (int i = 0; i < BT_; i++) {
            float val = (col < 128) ? sKP[i * 132 + col] : sV[i * 132 + (col - 128)];
            for (int j = 0; j < i; j++)
                val = fmaf(-sAkk[i * 65 + j], ssol[j * 256 + col], val);
            ssol[i * 256 + col] = val;
        }
    }
    __syncthreads();
    {
        int col = tid;
        size_t gb = ((size_t)bh * T_ + t0) * HD_ + (col & 127);
        for (int i = 0; i < BT_; i++) {
            float v = ssol[i * 256 + col];
            if (col < 128) g_pool[O_W + gb + (size_t)i * HD_] = v;
            else           g_pool[O_U + gb + (size_t)i * HD_] = v;
        }
    }
}

// ---------------- sequential scan over chunks; 8-way V split ----------------
__global__ void __launch_bounds__(256) scan_kernel(float* Sout) {
    extern __shared__ float sm[];
    float* sS   = sm;            // 128*16
    float* sW   = sm + 2048;     // 64*132
    float* sQG  = sm + 10496;
    float* sKN  = sm + 18944;
    float* sAqk = sm + 27392;    // 64*65
    float* sU   = sm + 31552;    // 64*16
    float* sT2  = sm + 32576;    // 64*16
    float* egl  = sm + 33600;    // 128

    int bh = blockIdx.x >> 3, vs = blockIdx.x & 7;
    int tid = threadIdx.x;
    int v = tid & 15, cq = tid >> 4;

    for (int e = tid; e < 2048; e += 256) sS[e] = 0.f;

    for (int n = 0; n < NCH_; n++) {
        __syncthreads();
        size_t tb = ((size_t)bh * T_ + n * BT_) * HD_;
        for (int e = tid; e < 8192; e += 256) {
            int t = e >> 7, c = e & 127;
            sW[t * 132 + c]  = g_pool[O_W + tb + e];
            sQG[t * 132 + c] = g_pool[O_QG + tb + e];
            sKN[t * 132 + c] = g_pool[O_KN + tb + e];
        }
        size_t ab = (size_t)(bh * NCH_ + n) * 4096;
        for (int e = tid; e < 4096; e += 256)
            sAqk[(e >> 6) * 65 + (e & 63)] = g_pool[O_AQK + ab + e];
        for (int e = tid; e < 1024; e += 256) {
            int t = e >> 4, vv = e & 15;
            sU[t * 16 + vv] = g_pool[O_U + tb + (size_t)t * HD_ + vs * 16 + vv];
        }
        if (tid < 128) egl[tid] = g_pool[O_EGL + (size_t)(bh * NCH_ + n) * HD_ + tid];
        __syncthreads();

        float t1[4] = {0.f, 0.f, 0.f, 0.f};
        for (int k = 0; k < 128; k++) {
            float sv = sS[k * 16 + v];
            #pragma unroll
            for (int r = 0; r < 4; r++)
                t1[r] = fmaf(sW[(cq * 4 + r) * 132 + k], sv, t1[r]);
        }
        #pragma unroll
        for (int r = 0; r < 4; r++) {
            int c = cq * 4 + r;
            sT2[c * 16 + v] = sU[c * 16 + v] - t1[r];
        }
        __syncthreads();

        float oa[4] = {0.f, 0.f, 0.f, 0.f};
        for (int k = 0; k < 128; k++) {
            float sv = sS[k * 16 + v];
            #pragma unroll
            for (int r = 0; r < 4; r++)
                oa[r] = fmaf(sQG[(cq * 4 + r) * 132 + k], sv, oa[r]);
        }
        for (int j = 0; j < 64; j++) {
            float tv = sT2[j * 16 + v];
            #pragma unroll
            for (int r = 0; r < 4; r++)
                oa[r] = fmaf(sAqk[(cq * 4 + r) * 65 + j], tv, oa[r]);
        }
        #pragma unroll
        for (int r = 0; r < 4; r++)
            g_pool[O_O + tb + (size_t)(cq * 4 + r) * HD_ + vs * 16 + v] = oa[r];
        __syncthreads();

        float acc[8];
        #pragma unroll
        for (int r = 0; r < 8; r++) acc[r] = 0.f;
        for (int c = 0; c < 64; c++) {
            float uv = sU[c * 16 + v];
            #pragma unroll
            for (int r = 0; r < 8; r++)
                acc[r] = fmaf(sKN[c * 132 + cq * 8 + r], uv, acc[r]);
        }
        #pragma unroll
        for (int r = 0; r < 8; r++) {
            int k = cq * 8 + r;
            sS[k * 16 + v] = egl[k] * (sS[k * 16 + v] + acc[r]);
        }
    }
    if (Sout) {
        __syncthreads();
        #pragma unroll
        for (int r = 0; r < 8; r++) {
            int k = cq * 8 + r;
            Sout[((size_t)bh * HD_ + k) * HD_ + vs * 16 + v] = sS[k * 16 + v];
        }
    }
}

// ---------------- RMS norm + gate ----------------
__global__ void __launch_bounds__(128) epilogue(const float* __restrict__ normw) {
    int h = blockIdx.x % H_;
    int bt = blockIdx.x / H_;
    int b = bt / T_, t = bt % T_;
    int d = threadIdx.x;
    float o = g_pool[O_O + ((size_t)(b * H_ + h) * T_ + t) * HD_ + d];
    float s = o * o;
    #pragma unroll
    for (int off = 16; off > 0; off >>= 1) s += __shfl_xor_sync(0xffffffffu, s, off);
    __shared__ float sh[4];
    int w = threadIdx.x >> 5;
    if ((threadIdx.x & 31) == 0) sh[w] = s;
    __syncthreads();
    float ms = (sh[0] + sh[1] + sh[2] + sh[3]) * (1.f / 128.f);
    size_t gi = (size_t)bt * C_ + h * HD_ + d;
    float z = g_pool[O_ZG + gi];
    float gate = 1.f / (1.f + expf(-z));
    g_pool[O_OG + gi] = o * rsqrtf(ms + EPS_RMS) * normw[d] * gate;
}

extern "C" void kernel_launch(void* const* d_in, const int* in_sizes, int n_in,
                              void* d_out, int out_size) {
    const float* x     = (const float*)d_in[0];
    const float* Wq    = (const float*)d_in[1];
    const float* Wk    = (const float*)d_in[2];
    const float* Wv    = (const float*)d_in[3];
    const float* cqw   = (const float*)d_in[4];
    const float* cqb   = (const float*)d_in[5];
    const float* ckw   = (const float*)d_in[6];
    const float* ckb   = (const float*)d_in[7];
    const float* cvw   = (const float*)d_in[8];
    const float* cvb   = (const float*)d_in[9];
    const float* Wad   = (const float*)d_in[10];
    const float* Wau   = (const float*)d_in[11];
    const float* Wgd   = (const float*)d_in[13];
    const float* Wgu   = (const float*)d_in[14];
    const float* normw = (const float*)d_in[15];
    const float* Wo    = (const float*)d_in[16];
    float* out = (float*)d_out;

    void* pv = nullptr;
    cudaGetSymbolAddress(&pv, g_pool);
    float* pool = (float*)pv;
    void* bv = nullptr;
    cudaGetSymbolAddress(&bv, g_bpool);
    __nv_bfloat16* bp = (__nv_bfloat16*)bv;

    cudaFuncSetAttribute(chunkprep, cudaFuncAttributeMaxDynamicSharedMemorySize, 42112 * 4);
    cudaFuncSetAttribute(scan_kernel, cudaFuncAttributeMaxDynamicSharedMemorySize, 33728 * 4);
    cudaFuncSetAttribute(tgemm, cudaFuncAttributeMaxDynamicSharedMemorySize, TG_SMEM);

    // 0) splits: x and all weights (transposed)
    cvt_split<<<(int)(SB_X / 4 / 256), 256>>>(x, bp + BO_XHI, bp + BO_XLO, (int)(SB_X / 4));
    cvt_splitT<<<dim3(C_ / 32, D_ / 32), 256>>>(Wq, bp + BO_WQTH, bp + BO_WQTL, D_, C_);
    cvt_splitT<<<dim3(C_ / 32, D_ / 32), 256>>>(Wk, bp + BO_WKTH, bp + BO_WKTL, D_, C_);
    cvt_splitT<<<dim3(C_ / 32, D_ / 32), 256>>>(Wv, bp + BO_WVTH, bp + BO_WVTL, D_, C_);
    cvt_splitT<<<dim3(D_ / 32, C_ / 32), 256>>>(Wo, bp + BO_WOTH, bp + BO_WOTL, C_, D_);
    cvt_splitT<<<dim3(HD_ / 32, D_ / 32), 256>>>(Wad, bp + BO_WADTH, bp + BO_WADTL, D_, HD_);
    cvt_splitT<<<dim3(HD_ / 32, D_ / 32), 256>>>(Wgd, bp + BO_WGDTH, bp + BO_WGDTL, D_, HD_);
    cvt_splitT<<<dim3(C_ / 32, HD_ / 32), 256>>>(Wau, bp + BO_WAUTH, bp + BO_WAUTL, HD_, C_);
    cvt_splitT<<<dim3(C_ / 32, HD_ / 32), 256>>>(Wgu, bp + BO_WGUTH, bp + BO_WGUTL, HD_, C_);

    // 1) projections (tensor cores, mma.sync)
    tgemm<<<dim3(C_ / 128, M_ / 128), 256, TG_SMEM>>>(bp + BO_XHI, bp + BO_XLO,
        bp + BO_WQTH, bp + BO_WQTL, pool + O_QLIN, M_, C_, D_);
    tgemm<<<dim3(C_ / 128, M_ / 128), 256, TG_SMEM>>>(bp + BO_XHI, bp + BO_XLO,
        bp + BO_WKTH, bp + BO_WKTL, pool + O_KLIN, M_, C_, D_);
    tgemm<<<dim3(C_ / 128, M_ / 128), 256, TG_SMEM>>>(bp + BO_XHI, bp + BO_XLO,
        bp + BO_WVTH, bp + BO_WVTL, pool + O_VLIN, M_, C_, D_);
    tgemm<<<dim3(1, M_ / 128), 256, TG_SMEM>>>(bp + BO_XHI, bp + BO_XLO,
        bp + BO_WADTH, bp + BO_WADTL, pool + O_AD, M_, HD_, D_);
    tgemm<<<dim3(1, M_ / 128), 256, TG_SMEM>>>(bp + BO_XHI, bp + BO_XLO,
        bp + BO_WGDTH, bp + BO_WGDTL, pool + O_GD, M_, HD_, D_);
    cvt_split<<<(int)(SB_AD / 4 / 256), 256>>>(pool + O_AD, bp + BO_ADH, bp + BO_ADL, (int)(SB_AD / 4));
    cvt_split<<<(int)(SB_AD / 4 / 256), 256>>>(pool + O_GD, bp + BO_GDH, bp + BO_GDL, (int)(SB_AD / 4));
    tgemm<<<dim3(C_ / 128, M_ / 128), 256, TG_SMEM>>>(bp + BO_ADH, bp + BO_ADL,
        bp + BO_WAUTH, bp + BO_WAUTL, pool + O_ZA, M_, C_, HD_);
    tgemm<<<dim3(C_ / 128, M_ / 128), 256, TG_SMEM>>>(bp + BO_GDH, bp + BO_GDL,
        bp + BO_WGUTH, bp + BO_WGUTL, pool + O_ZG, M_, C_, HD_);

    // 2) conv + norms + silu + g
    convheads<<<B_ * T_ * H_, 128>>>(cqw, cqb, ckw, ckb, cvw, cvb);

    // 3) per-chunk prep
    chunkprep<<<B_ * H_ * NCH_, 256, 42112 * 4>>>();

    // 4) sequential scan
    float* Sout = nullptr;
    size_t ysz = (size_t)M_ * D_;
    size_t ssz = (size_t)B_ * H_ * HD_ * HD_;
    if ((size_t)out_size >= ysz + ssz) Sout = out + ysz;
    scan_kernel<<<B_ * H_ * 8, 256, 33728 * 4>>>(Sout);

    // 5) rms norm + gate
    epilogue<<<B_ * T_ * H_, 128>>>(normw);

    // 6) final projection (tensor cores)
    cvt_split<<<(int)(SB_OG / 4 / 256), 256>>>(pool + O_OG, bp + BO_OGH, bp + BO_OGL, (int)(SB_OG / 4));
    tgemm<<<dim3(D_ / 128, M_ / 128), 256, TG_SMEM>>>(bp + BO_OGH, bp + BO_OGL,
        bp + BO_WOTH, bp + BO_WOTL, out, M_, D_, C_);
}